// round 11
// baseline (speedup 1.0000x reference)
#include <cuda_runtime.h>
#include <math.h>

#define NB 2
#define NS 2048
#define ND 1024
#define NH 16
#define NHD 64
#define MTOT (NB * NS)   // 4096

// Scratch (allocation-free rule: __device__ globals)
__device__ float g_q[NB * NH * NS * NHD];    // [B,H,S,HD], pre-scaled by 0.125*log2e
__device__ float g_k[NB * NH * NS * NHD];    // [B,H,S,HD]
__device__ float g_v[NB * NH * NHD * NS];    // [B,H,HD,S]  (transposed!)
__device__ float g_ctx[NB * NS * ND];        // tf32-rounded, perm16'd columns
__device__ float g_xr[MTOT * ND];            // x, tf32-rounded, perm16'd columns
__device__ float g_wr[4][ND * ND];           // W^T, tf32-rounded, perm16'd cols

// ---------------------------------------------------------------------------
// helpers
// ---------------------------------------------------------------------------
__device__ __forceinline__ float f2tf32(float x) {
    unsigned r;
    asm("cvt.rna.tf32.f32 %0, %1;" : "=r"(r) : "f"(x));
    return __uint_as_float(r);
}

__device__ __forceinline__ void mma_tf32(float (&c)[4], unsigned a0, unsigned a1,
                                         unsigned a2, unsigned a3, unsigned b0,
                                         unsigned b1) {
    asm volatile(
        "mma.sync.aligned.m16n8k8.row.col.f32.tf32.tf32.f32 "
        "{%0,%1,%2,%3}, {%4,%5,%6,%7}, {%8,%9}, {%0,%1,%2,%3};\n"
        : "+f"(c[0]), "+f"(c[1]), "+f"(c[2]), "+f"(c[3])
        : "r"(a0), "r"(a1), "r"(a2), "r"(a3), "r"(b0), "r"(b1));
}

__device__ __forceinline__ unsigned smaddr(const void* p) {
    return (unsigned)__cvta_generic_to_shared(p);
}
#define CP_ASYNC16(dst, src) \
    asm volatile("cp.async.cg.shared.global [%0], [%1], 16;\n" ::"r"(dst), "l"(src))
#define CP_COMMIT() asm volatile("cp.async.commit_group;\n")
#define CP_WAIT(n) asm volatile("cp.async.wait_group %0;\n" ::"n"(n))

// perm16: within each 16-block, place k at position (k%4)*4 + k/4, so the
// four k-values {t, t+4, t+8, t+12} (two mma k-groups' fragment slots for
// quad-thread t) are CONTIGUOUS -> one LDS.128 feeds two m16n8k8 mma.
__device__ __forceinline__ int perm16(int c) {
    return (c & ~15) | ((c & 3) << 2) | ((c >> 2) & 3);
}

#define LOG2E 1.44269504088896f

// ---------------------------------------------------------------------------
// Prep kernels: tf32-round + permute (x) / transpose+round+permute (W)
// ---------------------------------------------------------------------------
__global__ void __launch_bounds__(256)
round_x_kernel(const float* __restrict__ x) {
    const int f4 = blockIdx.x * 256 + threadIdx.x;
    const int base = f4 * 4;
    float4 v = *(const float4*)&x[base];
    g_xr[perm16(base + 0)] = f2tf32(v.x);
    g_xr[perm16(base + 1)] = f2tf32(v.y);
    g_xr[perm16(base + 2)] = f2tf32(v.z);
    g_xr[perm16(base + 3)] = f2tf32(v.w);
}

__global__ void __launch_bounds__(256)
round_w_kernel(const float* __restrict__ Wq, const float* __restrict__ Wk,
               const float* __restrict__ Wv, const float* __restrict__ Wo) {
    __shared__ float t[32][33];
    const float* W;
    if (blockIdx.z == 0) W = Wq;
    else if (blockIdx.z == 1) W = Wk;
    else if (blockIdx.z == 2) W = Wv;
    else W = Wo;
    float* out = &g_wr[blockIdx.z][0];

    const int k0 = blockIdx.x * 32, n0 = blockIdx.y * 32;
    const int tx = threadIdx.x, ty = threadIdx.y;
#pragma unroll
    for (int i = 0; i < 4; i++)
        t[ty + i * 8][tx] = W[(size_t)(k0 + ty + i * 8) * ND + n0 + tx];
    __syncthreads();
#pragma unroll
    for (int i = 0; i < 4; i++)
        out[(size_t)(n0 + ty + i * 8) * ND + k0 + perm16(tx)] =
            f2tf32(t[tx][ty + i * 8]);
}

// ---------------------------------------------------------------------------
// 256x128x32 TF32 GEMM tile, 2-stage cp.async pipeline, 1 CTA/SM.
// 8 warps in 4(M) x 2(N); warp tile 64x64 = 4x8 m16n8k8 atoms.
// perm16'd inputs: fragment loads are LDS.128 feeding 2 mma each
// (stride 48 floats -> conflict-free: phase start banks {0,4,..,28}).
// Smem: 2 stages of (A[256][48] + B[128][48]) = 147.5 KB.
// ---------------------------------------------------------------------------
#define GSTR 48
#define GEMM_ASTG (256 * GSTR)
#define GEMM_BSTG (128 * GSTR)
#define GEMM_STG (GEMM_ASTG + GEMM_BSTG)
#define GEMM_SMEM_FLOATS (2 * GEMM_STG)
#define GEMM_SMEM_BYTES (GEMM_SMEM_FLOATS * 4)

__device__ __forceinline__ void gemm_load_stage(const float* __restrict__ A,
                                                const float* __restrict__ Bt,
                                                float* stage, int mBase,
                                                int nBase, int k0, int tid) {
    float* sA = stage;
    float* sB = stage + GEMM_ASTG;
#pragma unroll
    for (int i = 0; i < 8; i++) {
        const int f4 = tid + i * 256;
        const int m = f4 >> 3, c4 = (f4 & 7) * 4;
        CP_ASYNC16(smaddr(&sA[m * GSTR + c4]),
                   &A[(size_t)(mBase + m) * ND + k0 + c4]);
    }
#pragma unroll
    for (int i = 0; i < 4; i++) {
        const int f4 = tid + i * 256;
        const int m = f4 >> 3, c4 = (f4 & 7) * 4;
        CP_ASYNC16(smaddr(&sB[m * GSTR + c4]),
                   &Bt[(size_t)(nBase + m) * ND + k0 + c4]);
    }
    CP_COMMIT();
}

__device__ __forceinline__ void sgemm_mma(const float* __restrict__ A,
                                          const float* __restrict__ Bt,
                                          float (&acc)[4][8][4]) {
    extern __shared__ float gsm[];

    const int tid = threadIdx.x;
    const int lane = tid & 31;
    const int wid = tid >> 5;
    const int warpM = wid >> 1;   // 0..3 -> 64 rows each
    const int warpN = wid & 1;    // 0..1 -> 64 cols each
    const int gid = lane >> 2;
    const int tig = lane & 3;
    const int mBase = blockIdx.y * 256;
    const int nBase = blockIdx.x * 128;

    // prologue: stage 0
    gemm_load_stage(A, Bt, gsm, mBase, nBase, 0, tid);

    for (int k0 = 0; k0 < ND; k0 += 32) {
        const int st = (k0 >> 5) & 1;
        if (k0 + 32 < ND) {
            gemm_load_stage(A, Bt, gsm + (st ^ 1) * GEMM_STG, mBase, nBase,
                            k0 + 32, tid);
            CP_WAIT(1);
        } else {
            CP_WAIT(0);
        }
        __syncthreads();

        const float* As = gsm + st * GEMM_STG;
        const float* Bs = As + GEMM_ASTG;
#pragma unroll
        for (int ks = 0; ks < 32; ks += 16) {
            float4 bf[8];
#pragma unroll
            for (int nt = 0; nt < 8; nt++)
                bf[nt] = *(const float4*)&Bs[(warpN * 64 + nt * 8 + gid) * GSTR + ks + 4 * tig];
#pragma unroll
            for (int mt = 0; mt < 4; mt++) {
                const int m = warpM * 64 + mt * 16;
                float4 lo = *(const float4*)&As[(m + gid) * GSTR + ks + 4 * tig];
                float4 hi = *(const float4*)&As[(m + gid + 8) * GSTR + ks + 4 * tig];
#pragma unroll
                for (int nt = 0; nt < 8; nt++) {
                    mma_tf32(acc[mt][nt], __float_as_uint(lo.x),
                             __float_as_uint(hi.x), __float_as_uint(lo.y),
                             __float_as_uint(hi.y), __float_as_uint(bf[nt].x),
                             __float_as_uint(bf[nt].y));
                    mma_tf32(acc[mt][nt], __float_as_uint(lo.z),
                             __float_as_uint(hi.z), __float_as_uint(lo.w),
                             __float_as_uint(hi.w), __float_as_uint(bf[nt].z),
                             __float_as_uint(bf[nt].w));
                }
            }
        }
        __syncthreads();
    }
}

// QKV projection. Q/K in [B,H,S,HD]; V stored TRANSPOSED [B,H,HD,S]. z=3.
// Q is pre-scaled by 0.125*log2e (softmax runs in exp2 domain).
__global__ void __launch_bounds__(256, 1)
qkv_proj_kernel(const float* __restrict__ bq, const float* __restrict__ bk,
                const float* __restrict__ bv) {
    const float* Bt;
    const float* bias;
    float sc;
    if (blockIdx.z == 0) { Bt = g_wr[0]; bias = bq; sc = 0.125f * LOG2E; }
    else if (blockIdx.z == 1) { Bt = g_wr[1]; bias = bk; sc = 1.0f; }
    else { Bt = g_wr[2]; bias = bv; sc = 1.0f; }

    float acc[4][8][4] = {};
    sgemm_mma(g_xr, Bt, acc);

    const int lane = threadIdx.x & 31;
    const int wid = threadIdx.x >> 5;
    const int warpM = wid >> 1, warpN = wid & 1;
    const int gid = lane >> 2, tig = lane & 3;
    const int mBase = blockIdx.y * 256, nBase = blockIdx.x * 128;

    if (blockIdx.z < 2) {
        float* out = (blockIdx.z == 0) ? g_q : g_k;
#pragma unroll
        for (int mt = 0; mt < 4; mt++) {
#pragma unroll
            for (int nt = 0; nt < 8; nt++) {
                const int c = nBase + warpN * 64 + nt * 8 + tig * 2;
                const int h = c >> 6, hd = c & 63;
                const float b0v = bias[c], b1v = bias[c + 1];
#pragma unroll
                for (int half = 0; half < 2; half++) {
                    const int r = mBase + warpM * 64 + mt * 16 + gid + half * 8;
                    const int b = r >> 11, s = r & 2047;
                    float2 val;
                    val.x = f2tf32((acc[mt][nt][half * 2 + 0] + b0v) * sc);
                    val.y = f2tf32((acc[mt][nt][half * 2 + 1] + b1v) * sc);
                    *(float2*)&out[(((b * NH + h) * NS + s) << 6) + hd] = val;
                }
            }
        }
    } else {
        // V: transposed store g_v[((b*NH+h)*NHD + hd)*NS + s]
#pragma unroll
        for (int mt = 0; mt < 4; mt++) {
#pragma unroll
            for (int nt = 0; nt < 8; nt++) {
                const int c = nBase + warpN * 64 + nt * 8 + tig * 2;
                const int h = c >> 6, hd = c & 63;
                const float b0v = bias[c], b1v = bias[c + 1];
#pragma unroll
                for (int half = 0; half < 2; half++) {
                    const int r = mBase + warpM * 64 + mt * 16 + gid + half * 8;
                    const int b = r >> 11, s = r & 2047;
                    float* base = &g_v[(size_t)((b * NH + h) * NHD + hd) * NS + s];
                    base[0] = f2tf32(acc[mt][nt][half * 2 + 0] + b0v);
                    base[NS] = f2tf32(acc[mt][nt][half * 2 + 1] + b1v);
                }
            }
        }
    }
}

// Output projection: out = ctx @ Wo + bo (ctx pre-rounded/perm16'd by flash)
__global__ void __launch_bounds__(256, 1)
out_proj_kernel(const float* __restrict__ bo, float* __restrict__ out) {
    float acc[4][8][4] = {};
    sgemm_mma(g_ctx, g_wr[3], acc);

    const int lane = threadIdx.x & 31;
    const int wid = threadIdx.x >> 5;
    const int warpM = wid >> 1, warpN = wid & 1;
    const int gid = lane >> 2, tig = lane & 3;
    const int mBase = blockIdx.y * 256, nBase = blockIdx.x * 128;

#pragma unroll
    for (int mt = 0; mt < 4; mt++) {
#pragma unroll
        for (int nt = 0; nt < 8; nt++) {
            const int c = nBase + warpN * 64 + nt * 8 + tig * 2;
            const float b0v = bo[c], b1v = bo[c + 1];
#pragma unroll
            for (int half = 0; half < 2; half++) {
                const int r = mBase + warpM * 64 + mt * 16 + gid + half * 8;
                float2 val;
                val.x = acc[mt][nt][half * 2 + 0] + b0v;
                val.y = acc[mt][nt][half * 2 + 1] + b1v;
                *(float2*)&out[(size_t)r * ND + c] = val;
            }
        }
    }
}

// ---------------------------------------------------------------------------
// FlashAttention-2, cp.async double-buffered K/V, register softmax in the
// exp2 domain (Q pre-scaled by 0.125*log2e at qkv time; exp2f = bare MUFU).
// ---------------------------------------------------------------------------
#define FQS 72
#define FQ_OFF 0
#define FK_OFF (128 * FQS)
#define FV_OFF (FK_OFF + 2 * 64 * FQS)
#define F_SMEM_FLOATS (FV_OFF + 2 * 64 * FQS)
#define F_SMEM_BYTES (F_SMEM_FLOATS * 4)

__global__ void __launch_bounds__(256, 2) flash_attn_kernel() {
    extern __shared__ float sm[];
    float* Qs = sm + FQ_OFF;

    const int tid = threadIdx.x;
    const int lane = tid & 31;
    const int wid = tid >> 5;        // 0..7, 16 query rows each
    const int gid = lane >> 2;       // 0..7
    const int tig = lane & 3;        // 0..3

    const int qt = gridDim.x - 1 - blockIdx.x;  // heavy tiles first
    const int h = blockIdx.y, b = blockIdx.z;
    const int bhBase = ((b * NH + h) * NS) << 6;
    const float* Qg = g_q + bhBase;
    const float* Kg = g_k + bhBase;
    const float* Vgt = g_v + bhBase;

#pragma unroll
    for (int i = 0; i < 8; i++) {
        const int f4 = tid + i * 256;
        const int r = f4 >> 4, c4 = (f4 & 15) * 4;
        CP_ASYNC16(smaddr(&Qs[r * FQS + c4]), &Qg[((qt * 128 + r) << 6) + c4]);
    }
#pragma unroll
    for (int i = 0; i < 4; i++) {
        const int f4 = tid + i * 256;
        const int r = f4 >> 4, c4 = (f4 & 15) * 4;
        CP_ASYNC16(smaddr(&sm[FK_OFF + r * FQS + c4]), &Kg[(r << 6) + c4]);
        CP_ASYNC16(smaddr(&sm[FV_OFF + r * FQS + c4]), &Vgt[r * NS + c4]);
    }
    CP_COMMIT();

    float o[8][4] = {};
    float m0 = -1e30f, m1 = -1e30f, l0 = 0.0f, l1 = 0.0f;
    const int wBase = wid * 16;
    const int rowG0 = qt * 128 + wBase + gid;
    const int ktMax = 2 * qt + 1;

    for (int kt = 0; kt <= ktMax; kt++) {
        const int st = kt & 1;
        if (kt < ktMax) {
            float* Kn = sm + FK_OFF + (st ^ 1) * 64 * FQS;
            float* Vn = sm + FV_OFF + (st ^ 1) * 64 * FQS;
            const float* Kgn = Kg + (((kt + 1) * 64) << 6);
            const float* Vgn = Vgt + (kt + 1) * 64;
#pragma unroll
            for (int i = 0; i < 4; i++) {
                const int f4 = tid + i * 256;
                const int r = f4 >> 4, c4 = (f4 & 15) * 4;
                CP_ASYNC16(smaddr(&Kn[r * FQS + c4]), &Kgn[(r << 6) + c4]);
                CP_ASYNC16(smaddr(&Vn[r * FQS + c4]), &Vgn[r * NS + c4]);
            }
            CP_COMMIT();
            CP_WAIT(1);
        } else {
            CP_WAIT(0);
        }
        __syncthreads();

        const float* Ks = sm + FK_OFF + st * 64 * FQS;
        const float* Vs = sm + FV_OFF + st * 64 * FQS;

        const bool active = (qt * 128 + wBase + 15) >= kt * 64;
        if (active) {
            // ---- S = Q @ K^T  (S is in log2 units) ----
            float s[8][4] = {};
#pragma unroll
            for (int kb = 0; kb < 8; kb++) {
                float2 qlo = *(const float2*)&Qs[(wBase + gid) * FQS + kb * 8 + 2 * tig];
                float2 qhi = *(const float2*)&Qs[(wBase + gid + 8) * FQS + kb * 8 + 2 * tig];
                const unsigned a0 = __float_as_uint(qlo.x);
                const unsigned a1 = __float_as_uint(qhi.x);
                const unsigned a2 = __float_as_uint(qlo.y);
                const unsigned a3 = __float_as_uint(qhi.y);
#pragma unroll
                for (int nt = 0; nt < 8; nt++) {
                    float2 bb = *(const float2*)&Ks[(nt * 8 + gid) * FQS + kb * 8 + 2 * tig];
                    mma_tf32(s[nt], a0, a1, a2, a3,
                             __float_as_uint(bb.x), __float_as_uint(bb.y));
                }
            }

            if (kt >= 2 * qt) {
#pragma unroll
                for (int nt = 0; nt < 8; nt++) {
                    const int col = kt * 64 + nt * 8 + 2 * tig;
                    if (col > rowG0) s[nt][0] = -1e30f;
                    if (col + 1 > rowG0) s[nt][1] = -1e30f;
                    if (col > rowG0 + 8) s[nt][2] = -1e30f;
                    if (col + 1 > rowG0 + 8) s[nt][3] = -1e30f;
                }
            }

            // ---- online softmax (exp2 domain, registers + quad shuffles) ----
            float mx0 = -1e30f, mx1 = -1e30f;
#pragma unroll
            for (int nt = 0; nt < 8; nt++) {
                mx0 = fmaxf(mx0, fmaxf(s[nt][0], s[nt][1]));
                mx1 = fmaxf(mx1, fmaxf(s[nt][2], s[nt][3]));
            }
            mx0 = fmaxf(mx0, __shfl_xor_sync(0xffffffffu, mx0, 1));
            mx0 = fmaxf(mx0, __shfl_xor_sync(0xffffffffu, mx0, 2));
            mx1 = fmaxf(mx1, __shfl_xor_sync(0xffffffffu, mx1, 1));
            mx1 = fmaxf(mx1, __shfl_xor_sync(0xffffffffu, mx1, 2));
            const float mn0 = fmaxf(m0, mx0);
            const float mn1 = fmaxf(m1, mx1);
            const float al0 = exp2f(m0 - mn0);
            const float al1 = exp2f(m1 - mn1);
            m0 = mn0; m1 = mn1;
            float sum0 = 0.0f, sum1 = 0.0f;
#pragma unroll
            for (int nt = 0; nt < 8; nt++) {
                float p0 = exp2f(s[nt][0] - mn0);
                float p1 = exp2f(s[nt][1] - mn0);
                float p2 = exp2f(s[nt][2] - mn1);
                float p3 = exp2f(s[nt][3] - mn1);
                sum0 += p0 + p1;
                sum1 += p2 + p3;
                s[nt][0] = f2tf32(p0);
                s[nt][1] = f2tf32(p1);
                s[nt][2] = f2tf32(p2);
                s[nt][3] = f2tf32(p3);
            }
            sum0 += __shfl_xor_sync(0xffffffffu, sum0, 1);
            sum0 += __shfl_xor_sync(0xffffffffu, sum0, 2);
            sum1 += __shfl_xor_sync(0xffffffffu, sum1, 1);
            sum1 += __shfl_xor_sync(0xffffffffu, sum1, 2);
            l0 = l0 * al0 + sum0;
            l1 = l1 * al1 + sum1;

            // ---- O = O*alpha + P @ V  (Vt[hd][key], float2 b-frags) ----
#pragma unroll
            for (int nt = 0; nt < 8; nt++) {
                o[nt][0] *= al0; o[nt][1] *= al0;
                o[nt][2] *= al1; o[nt][3] *= al1;
            }
#pragma unroll
            for (int kb = 0; kb < 8; kb++) {
                const unsigned a0 = __float_as_uint(s[kb][0]);
                const unsigned a1 = __float_as_uint(s[kb][2]);
                const unsigned a2 = __float_as_uint(s[kb][1]);
                const unsigned a3 = __float_as_uint(s[kb][3]);
#pragma unroll
                for (int nt = 0; nt < 8; nt++) {
                    float2 bb = *(const float2*)&Vs[(nt * 8 + gid) * FQS + kb * 8 + 2 * tig];
                    mma_tf32(o[nt], a0, a1, a2, a3,
                             __float_as_uint(bb.x), __float_as_uint(bb.y));
                }
            }
        }
        __syncthreads();
    }

    // ---- normalize, round, store ctx perm16'd in [B,S,D] for out_proj ----
    const float i0 = 1.0f / l0;
    const float i1 = 1.0f / l1;
    const int colBase = (h << 6) + 2 * tig;
    float* row0 = &g_ctx[(size_t)(b * NS + rowG0) * ND];
    float* row1 = &g_ctx[(size_t)(b * NS + rowG0 + 8) * ND];
#pragma unroll
    for (int nt = 0; nt < 8; nt++) {
        const int c = colBase + nt * 8;
        row0[perm16(c)] = f2tf32(o[nt][0] * i0);
        row0[perm16(c + 1)] = f2tf32(o[nt][1] * i0);
        row1[perm16(c)] = f2tf32(o[nt][2] * i1);
        row1[perm16(c + 1)] = f2tf32(o[nt][3] * i1);
    }
}

extern "C" void kernel_launch(void* const* d_in, const int* in_sizes, int n_in,
                              void* d_out, int out_size) {
    const float* x = (const float*)d_in[0];
    const float* Wq = (const float*)d_in[1];
    const float* bq = (const float*)d_in[2];
    const float* Wk = (const float*)d_in[3];
    const float* bk = (const float*)d_in[4];
    const float* Wv = (const float*)d_in[5];
    const float* bv = (const float*)d_in[6];
    const float* Wo = (const float*)d_in[7];
    const float* bo = (const float*)d_in[8];
    float* out = (float*)d_out;

    cudaFuncSetAttribute(flash_attn_kernel,
                         cudaFuncAttributeMaxDynamicSharedMemorySize,
                         F_SMEM_BYTES);
    cudaFuncSetAttribute(qkv_proj_kernel,
                         cudaFuncAttributeMaxDynamicSharedMemorySize,
                         GEMM_SMEM_BYTES);
    cudaFuncSetAttribute(out_proj_kernel,
                         cudaFuncAttributeMaxDynamicSharedMemorySize,
                         GEMM_SMEM_BYTES);

    round_x_kernel<<<MTOT * ND / 1024, 256>>>(x);
    dim3 gw(ND / 32, ND / 32, 4);
    round_w_kernel<<<gw, dim3(32, 8)>>>(Wq, Wk, Wv, Wo);

    dim3 g1(ND / 128, MTOT / 256, 3);
    qkv_proj_kernel<<<g1, 256, GEMM_SMEM_BYTES>>>(bq, bk, bv);

    dim3 g2(NS / 128, NH, NB);
    flash_attn_kernel<<<g2, 256, F_SMEM_BYTES>>>();

    dim3 g3(ND / 128, MTOT / 256);
    out_proj_kernel<<<g3, 256, GEMM_SMEM_BYTES>>>(bo, out);
}

// round 12
// speedup vs baseline: 1.0330x; 1.0330x over previous
#include <cuda_runtime.h>
#include <math.h>

#define NB 2
#define NS 2048
#define ND 1024
#define NH 16
#define NHD 64
#define MTOT (NB * NS)   // 4096

// Scratch (allocation-free rule: __device__ globals)
__device__ float g_q[NB * NH * NS * NHD];    // [B,H,S,HD]
__device__ float g_k[NB * NH * NS * NHD];    // [B,H,S,HD]
__device__ float g_v[NB * NH * NHD * NS];    // [B,H,HD,S]  (transposed!)
__device__ float g_ctx[NB * NS * ND];        // tf32-rounded, permk'd columns
__device__ float g_xr[MTOT * ND];            // x, tf32-rounded, permk'd columns
__device__ float g_wr[4][ND * ND];           // W^T, tf32-rounded, permk'd cols

// ---------------------------------------------------------------------------
// helpers
// ---------------------------------------------------------------------------
__device__ __forceinline__ float f2tf32(float x) {
    unsigned r;
    asm("cvt.rna.tf32.f32 %0, %1;" : "=r"(r) : "f"(x));
    return __uint_as_float(r);
}

__device__ __forceinline__ void mma_tf32(float (&c)[4], unsigned a0, unsigned a1,
                                         unsigned a2, unsigned a3, unsigned b0,
                                         unsigned b1) {
    asm volatile(
        "mma.sync.aligned.m16n8k8.row.col.f32.tf32.tf32.f32 "
        "{%0,%1,%2,%3}, {%4,%5,%6,%7}, {%8,%9}, {%0,%1,%2,%3};\n"
        : "+f"(c[0]), "+f"(c[1]), "+f"(c[2]), "+f"(c[3])
        : "r"(a0), "r"(a1), "r"(a2), "r"(a3), "r"(b0), "r"(b1));
}

__device__ __forceinline__ unsigned smaddr(const void* p) {
    return (unsigned)__cvta_generic_to_shared(p);
}
#define CP_ASYNC16(dst, src) \
    asm volatile("cp.async.cg.shared.global [%0], [%1], 16;\n" ::"r"(dst), "l"(src))
#define CP_COMMIT() asm volatile("cp.async.commit_group;\n")
#define CP_WAIT(n) asm volatile("cp.async.wait_group %0;\n" ::"n"(n))

// interleave k within 8-blocks so fragment pairs (k, k+4) are adjacent.
__device__ __forceinline__ int permk(int c) {
    return (c & ~7) | ((c & 3) << 1) | ((c >> 2) & 1);
}

// ---------------------------------------------------------------------------
// Prep kernels: tf32-round + permute (x) / transpose+round+permute (W)
// ---------------------------------------------------------------------------
__global__ void __launch_bounds__(256)
round_x_kernel(const float* __restrict__ x) {
    const int f4 = blockIdx.x * 256 + threadIdx.x;
    const int base = f4 * 4;
    float4 v = *(const float4*)&x[base];
    g_xr[permk(base + 0)] = f2tf32(v.x);
    g_xr[permk(base + 1)] = f2tf32(v.y);
    g_xr[permk(base + 2)] = f2tf32(v.z);
    g_xr[permk(base + 3)] = f2tf32(v.w);
}

__global__ void __launch_bounds__(256)
round_w_kernel(const float* __restrict__ Wq, const float* __restrict__ Wk,
               const float* __restrict__ Wv, const float* __restrict__ Wo) {
    __shared__ float t[32][33];
    const float* W;
    if (blockIdx.z == 0) W = Wq;
    else if (blockIdx.z == 1) W = Wk;
    else if (blockIdx.z == 2) W = Wv;
    else W = Wo;
    float* out = &g_wr[blockIdx.z][0];

    const int k0 = blockIdx.x * 32, n0 = blockIdx.y * 32;
    const int tx = threadIdx.x, ty = threadIdx.y;
#pragma unroll
    for (int i = 0; i < 4; i++)
        t[ty + i * 8][tx] = W[(size_t)(k0 + ty + i * 8) * ND + n0 + tx];
    __syncthreads();
#pragma unroll
    for (int i = 0; i < 4; i++)
        out[(size_t)(n0 + ty + i * 8) * ND + k0 + permk(tx)] =
            f2tf32(t[tx][ty + i * 8]);
}

// ---------------------------------------------------------------------------
// 256x128x32 TF32 GEMM tile, 2-stage cp.async pipeline, ONE barrier per
// chunk: {wait; sync; prefetch; compute}. 1 CTA/SM.
// 8 warps in 4(M) x 2(N); warp tile 64x64 = 4x8 m16n8k8 atoms.
// Smem: As[2][256][40] | Bs[2][128][40]  (122.9 KB)
// ---------------------------------------------------------------------------
#define GEMM_ASTG (256 * 40)
#define GEMM_BSTG (128 * 40)
#define GEMM_STG (GEMM_ASTG + GEMM_BSTG)
#define GEMM_SMEM_FLOATS (2 * GEMM_STG)
#define GEMM_SMEM_BYTES (GEMM_SMEM_FLOATS * 4)

__device__ __forceinline__ void gemm_load_stage(const float* __restrict__ A,
                                                const float* __restrict__ Bt,
                                                float* stage, int mBase,
                                                int nBase, int k0, int tid) {
    float* sA = stage;
    float* sB = stage + GEMM_ASTG;
#pragma unroll
    for (int i = 0; i < 8; i++) {
        const int f4 = tid + i * 256;
        const int m = f4 >> 3, c4 = (f4 & 7) * 4;
        CP_ASYNC16(smaddr(&sA[m * 40 + c4]),
                   &A[(size_t)(mBase + m) * ND + k0 + c4]);
    }
#pragma unroll
    for (int i = 0; i < 4; i++) {
        const int f4 = tid + i * 256;
        const int m = f4 >> 3, c4 = (f4 & 7) * 4;
        CP_ASYNC16(smaddr(&sB[m * 40 + c4]),
                   &Bt[(size_t)(nBase + m) * ND + k0 + c4]);
    }
    CP_COMMIT();
}

__device__ __forceinline__ void sgemm_mma(const float* __restrict__ A,
                                          const float* __restrict__ Bt,
                                          float (&acc)[4][8][4]) {
    extern __shared__ float gsm[];

    const int tid = threadIdx.x;
    const int lane = tid & 31;
    const int wid = tid >> 5;
    const int warpM = wid >> 1;   // 0..3 -> 64 rows each
    const int warpN = wid & 1;    // 0..1 -> 64 cols each
    const int gid = lane >> 2;
    const int tig = lane & 3;
    const int mBase = blockIdx.y * 256;
    const int nBase = blockIdx.x * 128;

    // prologue: stage 0
    gemm_load_stage(A, Bt, gsm, mBase, nBase, 0, tid);

    for (int k0 = 0; k0 < ND; k0 += 32) {
        const int st = (k0 >> 5) & 1;
        // Wait for this chunk's data, then ONE barrier. All warps past the
        // barrier have finished reading buffer st^1 (previous iteration), so
        // prefetching into it afterwards is safe. No trailing barrier.
        CP_WAIT(0);
        __syncthreads();
        if (k0 + 32 < ND)
            gemm_load_stage(A, Bt, gsm + (st ^ 1) * GEMM_STG, mBase, nBase,
                            k0 + 32, tid);

        const float* As = gsm + st * GEMM_STG;
        const float* Bs = As + GEMM_ASTG;
#pragma unroll
        for (int ks = 0; ks < 32; ks += 8) {
            unsigned bf[8][2];
#pragma unroll
            for (int nt = 0; nt < 8; nt++) {
                float2 bb = *(const float2*)&Bs[(warpN * 64 + nt * 8 + gid) * 40 + ks + 2 * tig];
                bf[nt][0] = __float_as_uint(bb.x);
                bf[nt][1] = __float_as_uint(bb.y);
            }
#pragma unroll
            for (int mt = 0; mt < 4; mt++) {
                const int m = warpM * 64 + mt * 16;
                float2 lo = *(const float2*)&As[(m + gid) * 40 + ks + 2 * tig];
                float2 hi = *(const float2*)&As[(m + gid + 8) * 40 + ks + 2 * tig];
                const unsigned a0 = __float_as_uint(lo.x);
                const unsigned a1 = __float_as_uint(hi.x);
                const unsigned a2 = __float_as_uint(lo.y);
                const unsigned a3 = __float_as_uint(hi.y);
#pragma unroll
                for (int nt = 0; nt < 8; nt++)
                    mma_tf32(acc[mt][nt], a0, a1, a2, a3, bf[nt][0], bf[nt][1]);
            }
        }
    }
}

// QKV projection. Q/K in [B,H,S,HD]; V stored TRANSPOSED [B,H,HD,S]. z=3.
__global__ void __launch_bounds__(256, 1)
qkv_proj_kernel(const float* __restrict__ bq, const float* __restrict__ bk,
                const float* __restrict__ bv) {
    const float* Bt;
    const float* bias;
    float sc;
    if (blockIdx.z == 0) { Bt = g_wr[0]; bias = bq; sc = 0.125f; }
    else if (blockIdx.z == 1) { Bt = g_wr[1]; bias = bk; sc = 1.0f; }
    else { Bt = g_wr[2]; bias = bv; sc = 1.0f; }

    float acc[4][8][4] = {};
    sgemm_mma(g_xr, Bt, acc);

    const int lane = threadIdx.x & 31;
    const int wid = threadIdx.x >> 5;
    const int warpM = wid >> 1, warpN = wid & 1;
    const int gid = lane >> 2, tig = lane & 3;
    const int mBase = blockIdx.y * 256, nBase = blockIdx.x * 128;

    if (blockIdx.z < 2) {
        float* out = (blockIdx.z == 0) ? g_q : g_k;
#pragma unroll
        for (int mt = 0; mt < 4; mt++) {
#pragma unroll
            for (int nt = 0; nt < 8; nt++) {
                const int c = nBase + warpN * 64 + nt * 8 + tig * 2;
                const int h = c >> 6, hd = c & 63;
                const float b0v = bias[c], b1v = bias[c + 1];
#pragma unroll
                for (int half = 0; half < 2; half++) {
                    const int r = mBase + warpM * 64 + mt * 16 + gid + half * 8;
                    const int b = r >> 11, s = r & 2047;
                    float2 val;
                    val.x = f2tf32((acc[mt][nt][half * 2 + 0] + b0v) * sc);
                    val.y = f2tf32((acc[mt][nt][half * 2 + 1] + b1v) * sc);
                    *(float2*)&out[(((b * NH + h) * NS + s) << 6) + hd] = val;
                }
            }
        }
    } else {
        // V: transposed store g_v[((b*NH+h)*NHD + hd)*NS + s]
#pragma unroll
        for (int mt = 0; mt < 4; mt++) {
#pragma unroll
            for (int nt = 0; nt < 8; nt++) {
                const int c = nBase + warpN * 64 + nt * 8 + tig * 2;
                const int h = c >> 6, hd = c & 63;
                const float b0v = bias[c], b1v = bias[c + 1];
#pragma unroll
                for (int half = 0; half < 2; half++) {
                    const int r = mBase + warpM * 64 + mt * 16 + gid + half * 8;
                    const int b = r >> 11, s = r & 2047;
                    float* base = &g_v[(size_t)((b * NH + h) * NHD + hd) * NS + s];
                    base[0] = f2tf32(acc[mt][nt][half * 2 + 0] + b0v);
                    base[NS] = f2tf32(acc[mt][nt][half * 2 + 1] + b1v);
                }
            }
        }
    }
}

// Output projection: out = ctx @ Wo + bo (ctx pre-rounded/permuted by flash)
__global__ void __launch_bounds__(256, 1)
out_proj_kernel(const float* __restrict__ bo, float* __restrict__ out) {
    float acc[4][8][4] = {};
    sgemm_mma(g_ctx, g_wr[3], acc);

    const int lane = threadIdx.x & 31;
    const int wid = threadIdx.x >> 5;
    const int warpM = wid >> 1, warpN = wid & 1;
    const int gid = lane >> 2, tig = lane & 3;
    const int mBase = blockIdx.y * 256, nBase = blockIdx.x * 128;

#pragma unroll
    for (int mt = 0; mt < 4; mt++) {
#pragma unroll
        for (int nt = 0; nt < 8; nt++) {
            const int c = nBase + warpN * 64 + nt * 8 + tig * 2;
            const float b0v = bo[c], b1v = bo[c + 1];
#pragma unroll
            for (int half = 0; half < 2; half++) {
                const int r = mBase + warpM * 64 + mt * 16 + gid + half * 8;
                float2 val;
                val.x = acc[mt][nt][half * 2 + 0] + b0v;
                val.y = acc[mt][nt][half * 2 + 1] + b1v;
                *(float2*)&out[(size_t)r * ND + c] = val;
            }
        }
    }
}

// ---------------------------------------------------------------------------
// FlashAttention-2, cp.async double-buffered K/V, register softmax.
// ONE barrier per key tile: {wait; sync; prefetch; compute}.
// ---------------------------------------------------------------------------
#define FQS 72
#define FQ_OFF 0
#define FK_OFF (128 * FQS)
#define FV_OFF (FK_OFF + 2 * 64 * FQS)
#define F_SMEM_FLOATS (FV_OFF + 2 * 64 * FQS)
#define F_SMEM_BYTES (F_SMEM_FLOATS * 4)

__global__ void __launch_bounds__(256, 2) flash_attn_kernel() {
    extern __shared__ float sm[];
    float* Qs = sm + FQ_OFF;

    const int tid = threadIdx.x;
    const int lane = tid & 31;
    const int wid = tid >> 5;        // 0..7, 16 query rows each
    const int gid = lane >> 2;       // 0..7
    const int tig = lane & 3;        // 0..3

    const int qt = gridDim.x - 1 - blockIdx.x;  // heavy tiles first
    const int h = blockIdx.y, b = blockIdx.z;
    const int bhBase = ((b * NH + h) * NS) << 6;
    const float* Qg = g_q + bhBase;
    const float* Kg = g_k + bhBase;
    const float* Vgt = g_v + bhBase;  // [HD][S] block

    // prologue: async-load Q tile + K0 + V0 (group 0)
#pragma unroll
    for (int i = 0; i < 8; i++) {
        const int f4 = tid + i * 256;
        const int r = f4 >> 4, c4 = (f4 & 15) * 4;
        CP_ASYNC16(smaddr(&Qs[r * FQS + c4]), &Qg[((qt * 128 + r) << 6) + c4]);
    }
#pragma unroll
    for (int i = 0; i < 4; i++) {
        const int f4 = tid + i * 256;
        const int r = f4 >> 4, c4 = (f4 & 15) * 4;
        CP_ASYNC16(smaddr(&sm[FK_OFF + r * FQS + c4]), &Kg[(r << 6) + c4]);
        CP_ASYNC16(smaddr(&sm[FV_OFF + r * FQS + c4]), &Vgt[r * NS + c4]);
    }
    CP_COMMIT();

    float o[8][4] = {};
    float m0 = -1e30f, m1 = -1e30f, l0 = 0.0f, l1 = 0.0f;
    const int wBase = wid * 16;
    const int rowG0 = qt * 128 + wBase + gid;
    const int ktMax = 2 * qt + 1;

    for (int kt = 0; kt <= ktMax; kt++) {
        const int st = kt & 1;
        // Wait for this tile's K/V, one barrier, then prefetch next tile into
        // the buffer all warps just finished reading (safe past the barrier).
        CP_WAIT(0);
        __syncthreads();
        if (kt < ktMax) {
            float* Kn = sm + FK_OFF + (st ^ 1) * 64 * FQS;
            float* Vn = sm + FV_OFF + (st ^ 1) * 64 * FQS;
            const float* Kgn = Kg + (((kt + 1) * 64) << 6);
            const float* Vgn = Vgt + (kt + 1) * 64;
#pragma unroll
            for (int i = 0; i < 4; i++) {
                const int f4 = tid + i * 256;
                const int r = f4 >> 4, c4 = (f4 & 15) * 4;
                CP_ASYNC16(smaddr(&Kn[r * FQS + c4]), &Kgn[(r << 6) + c4]);
                CP_ASYNC16(smaddr(&Vn[r * FQS + c4]), &Vgn[r * NS + c4]);
            }
            CP_COMMIT();
        }

        const float* Ks = sm + FK_OFF + st * 64 * FQS;
        const float* Vs = sm + FV_OFF + st * 64 * FQS;

        // Warp-level skip: rows of this warp all above the key range -> masked
        const bool active = (qt * 128 + wBase + 15) >= kt * 64;
        if (active) {
            // ---- S = Q @ K^T ----
            float s[8][4] = {};
#pragma unroll
            for (int kb = 0; kb < 8; kb++) {
                float2 qlo = *(const float2*)&Qs[(wBase + gid) * FQS + kb * 8 + 2 * tig];
                float2 qhi = *(const float2*)&Qs[(wBase + gid + 8) * FQS + kb * 8 + 2 * tig];
                const unsigned a0 = __float_as_uint(qlo.x);
                const unsigned a1 = __float_as_uint(qhi.x);
                const unsigned a2 = __float_as_uint(qlo.y);
                const unsigned a3 = __float_as_uint(qhi.y);
#pragma unroll
                for (int nt = 0; nt < 8; nt++) {
                    float2 bb = *(const float2*)&Ks[(nt * 8 + gid) * FQS + kb * 8 + 2 * tig];
                    mma_tf32(s[nt], a0, a1, a2, a3,
                             __float_as_uint(bb.x), __float_as_uint(bb.y));
                }
            }

            // ---- causal mask (last two kt tiles only) ----
            if (kt >= 2 * qt) {
#pragma unroll
                for (int nt = 0; nt < 8; nt++) {
                    const int col = kt * 64 + nt * 8 + 2 * tig;
                    if (col > rowG0) s[nt][0] = -1e30f;
                    if (col + 1 > rowG0) s[nt][1] = -1e30f;
                    if (col > rowG0 + 8) s[nt][2] = -1e30f;
                    if (col + 1 > rowG0 + 8) s[nt][3] = -1e30f;
                }
            }

            // ---- online softmax (registers + quad shuffles) ----
            float mx0 = -1e30f, mx1 = -1e30f;
#pragma unroll
            for (int nt = 0; nt < 8; nt++) {
                mx0 = fmaxf(mx0, fmaxf(s[nt][0], s[nt][1]));
                mx1 = fmaxf(mx1, fmaxf(s[nt][2], s[nt][3]));
            }
            mx0 = fmaxf(mx0, __shfl_xor_sync(0xffffffffu, mx0, 1));
            mx0 = fmaxf(mx0, __shfl_xor_sync(0xffffffffu, mx0, 2));
            mx1 = fmaxf(mx1, __shfl_xor_sync(0xffffffffu, mx1, 1));
            mx1 = fmaxf(mx1, __shfl_xor_sync(0xffffffffu, mx1, 2));
            const float mn0 = fmaxf(m0, mx0);
            const float mn1 = fmaxf(m1, mx1);
            const float al0 = __expf(m0 - mn0);
            const float al1 = __expf(m1 - mn1);
            m0 = mn0; m1 = mn1;
            float sum0 = 0.0f, sum1 = 0.0f;
#pragma unroll
            for (int nt = 0; nt < 8; nt++) {
                float p0 = __expf(s[nt][0] - mn0);
                float p1 = __expf(s[nt][1] - mn0);
                float p2 = __expf(s[nt][2] - mn1);
                float p3 = __expf(s[nt][3] - mn1);
                sum0 += p0 + p1;
                sum1 += p2 + p3;
                s[nt][0] = f2tf32(p0);
                s[nt][1] = f2tf32(p1);
                s[nt][2] = f2tf32(p2);
                s[nt][3] = f2tf32(p3);
            }
            sum0 += __shfl_xor_sync(0xffffffffu, sum0, 1);
            sum0 += __shfl_xor_sync(0xffffffffu, sum0, 2);
            sum1 += __shfl_xor_sync(0xffffffffu, sum1, 1);
            sum1 += __shfl_xor_sync(0xffffffffu, sum1, 2);
            l0 = l0 * al0 + sum0;
            l1 = l1 * al1 + sum1;

            // ---- O = O*alpha + P @ V  (Vt[hd][key], float2 b-frags) ----
#pragma unroll
            for (int nt = 0; nt < 8; nt++) {
                o[nt][0] *= al0; o[nt][1] *= al0;
                o[nt][2] *= al1; o[nt][3] *= al1;
            }
#pragma unroll
            for (int kb = 0; kb < 8; kb++) {
                const unsigned a0 = __float_as_uint(s[kb][0]);
                const unsigned a1 = __float_as_uint(s[kb][2]);
                const unsigned a2 = __float_as_uint(s[kb][1]);
                const unsigned a3 = __float_as_uint(s[kb][3]);
#pragma unroll
                for (int nt = 0; nt < 8; nt++) {
                    float2 bb = *(const float2*)&Vs[(nt * 8 + gid) * FQS + kb * 8 + 2 * tig];
                    mma_tf32(o[nt], a0, a1, a2, a3,
                             __float_as_uint(bb.x), __float_as_uint(bb.y));
                }
            }
        }
    }

    // ---- normalize, round, store ctx permk'd in [B,S,D] for out_proj ----
    const float i0 = 1.0f / l0;
    const float i1 = 1.0f / l1;
    const int colBase = (h << 6) + 2 * tig;
    float* row0 = &g_ctx[(size_t)(b * NS + rowG0) * ND];
    float* row1 = &g_ctx[(size_t)(b * NS + rowG0 + 8) * ND];
#pragma unroll
    for (int nt = 0; nt < 8; nt++) {
        const int c = colBase + nt * 8;
        row0[permk(c)] = f2tf32(o[nt][0] * i0);
        row0[permk(c + 1)] = f2tf32(o[nt][1] * i0);
        row1[permk(c)] = f2tf32(o[nt][2] * i1);
        row1[permk(c + 1)] = f2tf32(o[nt][3] * i1);
    }
}

extern "C" void kernel_launch(void* const* d_in, const int* in_sizes, int n_in,
                              void* d_out, int out_size) {
    const float* x = (const float*)d_in[0];
    const float* Wq = (const float*)d_in[1];
    const float* bq = (const float*)d_in[2];
    const float* Wk = (const float*)d_in[3];
    const float* bk = (const float*)d_in[4];
    const float* Wv = (const float*)d_in[5];
    const float* bv = (const float*)d_in[6];
    const float* Wo = (const float*)d_in[7];
    const float* bo = (const float*)d_in[8];
    float* out = (float*)d_out;

    cudaFuncSetAttribute(flash_attn_kernel,
                         cudaFuncAttributeMaxDynamicSharedMemorySize,
                         F_SMEM_BYTES);
    cudaFuncSetAttribute(qkv_proj_kernel,
                         cudaFuncAttributeMaxDynamicSharedMemorySize,
                         GEMM_SMEM_BYTES);
    cudaFuncSetAttribute(out_proj_kernel,
                         cudaFuncAttributeMaxDynamicSharedMemorySize,
                         GEMM_SMEM_BYTES);

    // Prep: round + permute x; transpose + round + permute all W
    round_x_kernel<<<MTOT * ND / 1024, 256>>>(x);
    dim3 gw(ND / 32, ND / 32, 4);
    round_w_kernel<<<gw, dim3(32, 8)>>>(Wq, Wk, Wv, Wo);

    dim3 g1(ND / 128, MTOT / 256, 3);
    qkv_proj_kernel<<<g1, 256, GEMM_SMEM_BYTES>>>(bq, bk, bv);

    dim3 g2(NS / 128, NH, NB);
    flash_attn_kernel<<<g2, 256, F_SMEM_BYTES>>>();

    dim3 g3(ND / 128, MTOT / 256);
    out_proj_kernel<<<g3, 256, GEMM_SMEM_BYTES>>>(bo, out);
}